// round 3
// baseline (speedup 1.0000x reference)
#include <cuda_runtime.h>

#define DIM 128
#define NH  8
#define MAXN 50176

// ---------------- scratch (no allocations allowed) ----------------
__device__ float g_h[MAXN * DIM];     // transformed features (per layer)
__device__ float g_x2[MAXN * DIM];    // layer-1 output (relu'd), input to layer 2
__device__ float g_asrc[MAXN * NH];
__device__ float g_adst[MAXN * NH];
__device__ float g_max[MAXN * NH];
__device__ float g_den[MAXN * NH];

__device__ __forceinline__ float leaky(float v) { return v > 0.f ? v : 0.2f * v; }

// float atomic max via signed int max / unsigned min trick (init with -inf)
__device__ __forceinline__ void atomicMaxF(float* addr, float val) {
    if (val >= 0.f) atomicMax((int*)addr, __float_as_int(val));
    else            atomicMin((unsigned int*)addr, __float_as_uint(val));
}

// ---------------- C[N,128] = A[N,128] * B[128,128] ----------------
__global__ void gemm128(const float* __restrict__ A, const float* __restrict__ B,
                        float* __restrict__ Cm, int N) {
    __shared__ float As[8][128];   // transposed A chunk: As[k][row]
    __shared__ float Bs[8][128];   // Bs[k][col]
    const int tid = threadIdx.x;           // 256 threads
    const int tx = tid & 15;               // col group
    const int ty = tid >> 4;               // row group
    const int rowBase = blockIdx.x * 128;
    const int arow  = tid >> 1;            // 0..127
    const int akoff = (tid & 1) * 4;
    const int brow  = tid >> 5;            // 0..7
    const int bcol  = (tid & 31) * 4;

    float acc[8][8];
#pragma unroll
    for (int i = 0; i < 8; i++)
#pragma unroll
        for (int j = 0; j < 8; j++) acc[i][j] = 0.f;

    for (int k0 = 0; k0 < 128; k0 += 8) {
        float4 av = make_float4(0.f, 0.f, 0.f, 0.f);
        int gr = rowBase + arow;
        if (gr < N) av = *(const float4*)&A[(size_t)gr * DIM + k0 + akoff];
        As[akoff + 0][arow] = av.x;
        As[akoff + 1][arow] = av.y;
        As[akoff + 2][arow] = av.z;
        As[akoff + 3][arow] = av.w;
        *(float4*)&Bs[brow][bcol] = *(const float4*)&B[(size_t)(k0 + brow) * DIM + bcol];
        __syncthreads();
#pragma unroll
        for (int kr = 0; kr < 8; kr++) {
            float a[8], b[8];
#pragma unroll
            for (int i = 0; i < 8; i++) a[i] = As[kr][ty * 8 + i];
#pragma unroll
            for (int j = 0; j < 8; j++) b[j] = Bs[kr][tx * 8 + j];
#pragma unroll
            for (int i = 0; i < 8; i++)
#pragma unroll
                for (int j = 0; j < 8; j++) acc[i][j] += a[i] * b[j];
        }
        __syncthreads();
    }
#pragma unroll
    for (int i = 0; i < 8; i++) {
        int gr = rowBase + ty * 8 + i;
        if (gr < N) {
            *(float4*)&Cm[(size_t)gr * DIM + tx * 8]     =
                make_float4(acc[i][0], acc[i][1], acc[i][2], acc[i][3]);
            *(float4*)&Cm[(size_t)gr * DIM + tx * 8 + 4] =
                make_float4(acc[i][4], acc[i][5], acc[i][6], acc[i][7]);
        }
    }
}

// a_src[n,h] = dot(h[n,h,:], att_src[h,:]); same for a_dst
__global__ void attn_k(const float* __restrict__ hf, const float* __restrict__ atts,
                       const float* __restrict__ attd, float* __restrict__ asrc,
                       float* __restrict__ adst, int N) {
    int t = blockIdx.x * blockDim.x + threadIdx.x;
    if (t >= N * NH) return;
    int n = t >> 3, hd = t & 7;
    const float* hp = &hf[(size_t)n * DIM + hd * 16];
    const float* sp = &atts[hd * 16];
    const float* dp = &attd[hd * 16];
    float ss = 0.f, sd = 0.f;
#pragma unroll
    for (int q = 0; q < 16; q += 4) {
        float4 hv = *(const float4*)&hp[q];
        float4 sv = *(const float4*)&sp[q];
        float4 dv = *(const float4*)&dp[q];
        ss += hv.x * sv.x + hv.y * sv.y + hv.z * sv.z + hv.w * sv.w;
        sd += hv.x * dv.x + hv.y * dv.y + hv.z * dv.z + hv.w * dv.w;
    }
    asrc[t] = ss;
    adst[t] = sd;
}

// init softmax scratch + bias-initialize the output accumulator
__global__ void prep_k(float* __restrict__ mx, float* __restrict__ den,
                       float* __restrict__ outbuf, const float* __restrict__ bias, int N) {
    int t = blockIdx.x * blockDim.x + threadIdx.x;
    if (t < N * NH) { mx[t] = __int_as_float(0xff800000); den[t] = 0.f; }
    if (t < N * DIM) outbuf[t] = bias[t & (DIM - 1)];
}

__global__ void edge_max_k(const int* __restrict__ ei, int E, int N,
                           const float* __restrict__ asrc, const float* __restrict__ adst,
                           float* __restrict__ mx) {
    int e = blockIdx.x * blockDim.x + threadIdx.x;
    int T = E + N;
    if (e >= T) return;
    int s, d;
    if (e < E) { s = ei[e]; d = ei[E + e]; } else { s = e - E; d = s; }
    float4 s0 = *(const float4*)&asrc[s * NH];
    float4 s1 = *(const float4*)&asrc[s * NH + 4];
    float4 d0 = *(const float4*)&adst[d * NH];
    float4 d1 = *(const float4*)&adst[d * NH + 4];
    float ev[8] = { s0.x + d0.x, s0.y + d0.y, s0.z + d0.z, s0.w + d0.w,
                    s1.x + d1.x, s1.y + d1.y, s1.z + d1.z, s1.w + d1.w };
#pragma unroll
    for (int h = 0; h < NH; h++) atomicMaxF(&mx[d * NH + h], leaky(ev[h]));
}

__global__ void edge_sum_k(const int* __restrict__ ei, int E, int N,
                           const float* __restrict__ asrc, const float* __restrict__ adst,
                           const float* __restrict__ mx, float* __restrict__ den) {
    int e = blockIdx.x * blockDim.x + threadIdx.x;
    int T = E + N;
    if (e >= T) return;
    int s, d;
    if (e < E) { s = ei[e]; d = ei[E + e]; } else { s = e - E; d = s; }
    float4 s0 = *(const float4*)&asrc[s * NH];
    float4 s1 = *(const float4*)&asrc[s * NH + 4];
    float4 d0 = *(const float4*)&adst[d * NH];
    float4 d1 = *(const float4*)&adst[d * NH + 4];
    float4 m0 = *(const float4*)&mx[d * NH];
    float4 m1 = *(const float4*)&mx[d * NH + 4];
    float ev[8] = { s0.x + d0.x, s0.y + d0.y, s0.z + d0.z, s0.w + d0.w,
                    s1.x + d1.x, s1.y + d1.y, s1.z + d1.z, s1.w + d1.w };
    float mm[8] = { m0.x, m0.y, m0.z, m0.w, m1.x, m1.y, m1.z, m1.w };
#pragma unroll
    for (int h = 0; h < NH; h++)
        atomicAdd(&den[d * NH + h], expf(leaky(ev[h]) - mm[h]));
}

// one warp per edge: lane l handles cols [4l, 4l+4), head = l>>2
__global__ void edge_aggr_k(const int* __restrict__ ei, int E, int N,
                            const float* __restrict__ asrc, const float* __restrict__ adst,
                            const float* __restrict__ mx, const float* __restrict__ den,
                            const float* __restrict__ hf, float* __restrict__ outbuf) {
    int gw = (blockIdx.x * blockDim.x + threadIdx.x) >> 5;
    int lane = threadIdx.x & 31;
    int T = E + N;
    if (gw >= T) return;
    int s, d;
    if (gw < E) { s = ei[gw]; d = ei[E + gw]; } else { s = gw - E; d = s; }
    float alpha = 0.f;
    if (lane < NH) {
        float e = leaky(asrc[s * NH + lane] + adst[d * NH + lane]);
        alpha = expf(e - mx[d * NH + lane]) / den[d * NH + lane];
    }
    float a = __shfl_sync(0xffffffffu, alpha, lane >> 2);
    float4 hv = *(const float4*)&hf[(size_t)s * DIM + lane * 4];
    float* op = &outbuf[(size_t)d * DIM + lane * 4];
    atomicAdd(op + 0, a * hv.x);
    atomicAdd(op + 1, a * hv.y);
    atomicAdd(op + 2, a * hv.z);
    atomicAdd(op + 3, a * hv.w);
}

__global__ void relu_k(float* __restrict__ p, int n) {
    int t = blockIdx.x * blockDim.x + threadIdx.x;
    if (t < n) p[t] = fmaxf(p[t], 0.f);
}

// ---------------- host ----------------
static void run_layer(const float* xin, const int* ei, int N, int E,
                      const float* W, const float* as_, const float* ad_,
                      const float* bias, float* hbuf, float* asrc, float* adst,
                      float* mx, float* den, float* outbuf) {
    int T = E + N;
    gemm128<<<(N + 127) / 128, 256>>>(xin, W, hbuf, N);
    attn_k<<<(N * NH + 255) / 256, 256>>>(hbuf, as_, ad_, asrc, adst, N);
    prep_k<<<(N * DIM + 255) / 256, 256>>>(mx, den, outbuf, bias, N);
    edge_max_k<<<(T + 255) / 256, 256>>>(ei, E, N, asrc, adst, mx);
    edge_sum_k<<<(T + 255) / 256, 256>>>(ei, E, N, asrc, adst, mx, den);
    edge_aggr_k<<<(T + 7) / 8, 256>>>(ei, E, N, asrc, adst, mx, den, hbuf, outbuf);
}

extern "C" void kernel_launch(void* const* d_in, const int* in_sizes, int n_in,
                              void* d_out, int out_size) {
    const float* x   = (const float*)d_in[0];
    const int*   ei  = (const int*)d_in[1];   // int32 (JAX x64 disabled downcasts int64)
    const float* W1  = (const float*)d_in[2];
    const float* as1 = (const float*)d_in[3];
    const float* ad1 = (const float*)d_in[4];
    const float* b1  = (const float*)d_in[5];
    const float* W2  = (const float*)d_in[6];
    const float* as2 = (const float*)d_in[7];
    const float* ad2 = (const float*)d_in[8];
    const float* b2  = (const float*)d_in[9];
    float* out = (float*)d_out;

    int N = in_sizes[0] / DIM;
    int E = in_sizes[1] / 2;

    float *hbuf, *x2, *asrc, *adst, *mx, *den;
    cudaGetSymbolAddress((void**)&hbuf, g_h);
    cudaGetSymbolAddress((void**)&x2,   g_x2);
    cudaGetSymbolAddress((void**)&asrc, g_asrc);
    cudaGetSymbolAddress((void**)&adst, g_adst);
    cudaGetSymbolAddress((void**)&mx,   g_max);
    cudaGetSymbolAddress((void**)&den,  g_den);

    // layer 1: out -> g_x2 (bias-initialized), then relu in place
    run_layer(x, ei, N, E, W1, as1, ad1, b1, hbuf, asrc, adst, mx, den, x2);
    relu_k<<<(N * DIM + 255) / 256, 256>>>(x2, N * DIM);
    // layer 2: out -> d_out (bias-initialized)
    run_layer(x2, ei, N, E, W2, as2, ad2, b2, hbuf, asrc, adst, mx, den, out);
}

// round 4
// speedup vs baseline: 2.6500x; 2.6500x over previous
#include <cuda_runtime.h>

#define DIM 128
#define NH  8
#define MAXN 50176
#define MAXT 1048576   // max edges incl. self loops

// ---------------- scratch (no allocations allowed) ----------------
__device__ float g_h[MAXN * DIM];
__device__ float g_x2[MAXN * DIM];
__device__ float g_asrc[MAXN * NH];
__device__ float g_adst[MAXN * NH];
__device__ int   g_cnt[MAXN + 1];       // degree counts
__device__ int   g_row[MAXN + 1];       // CSR row offsets
__device__ int   g_cur[MAXN];           // scatter cursors
__device__ int   g_bsum[256];           // block sums for scan
__device__ int   g_csrc[MAXT];          // CSR src ids

__device__ __forceinline__ float leaky(float v) { return v > 0.f ? v : 0.2f * v; }

// ---------------- C[N,128] = A[N,128] * B[128,128] ----------------
__global__ void gemm128(const float* __restrict__ A, const float* __restrict__ B,
                        float* __restrict__ Cm, int N) {
    __shared__ float As[8][128];
    __shared__ float Bs[8][128];
    const int tid = threadIdx.x;           // 256 threads
    const int tx = tid & 15;
    const int ty = tid >> 4;
    const int rowBase = blockIdx.x * 128;
    const int arow  = tid >> 1;
    const int akoff = (tid & 1) * 4;
    const int brow  = tid >> 5;
    const int bcol  = (tid & 31) * 4;

    float acc[8][8];
#pragma unroll
    for (int i = 0; i < 8; i++)
#pragma unroll
        for (int j = 0; j < 8; j++) acc[i][j] = 0.f;

    for (int k0 = 0; k0 < 128; k0 += 8) {
        float4 av = make_float4(0.f, 0.f, 0.f, 0.f);
        int gr = rowBase + arow;
        if (gr < N) av = *(const float4*)&A[(size_t)gr * DIM + k0 + akoff];
        As[akoff + 0][arow] = av.x;
        As[akoff + 1][arow] = av.y;
        As[akoff + 2][arow] = av.z;
        As[akoff + 3][arow] = av.w;
        *(float4*)&Bs[brow][bcol] = *(const float4*)&B[(size_t)(k0 + brow) * DIM + bcol];
        __syncthreads();
#pragma unroll
        for (int kr = 0; kr < 8; kr++) {
            float a[8], b[8];
#pragma unroll
            for (int i = 0; i < 8; i++) a[i] = As[kr][ty * 8 + i];
#pragma unroll
            for (int j = 0; j < 8; j++) b[j] = Bs[kr][tx * 8 + j];
#pragma unroll
            for (int i = 0; i < 8; i++)
#pragma unroll
                for (int j = 0; j < 8; j++) acc[i][j] += a[i] * b[j];
        }
        __syncthreads();
    }
#pragma unroll
    for (int i = 0; i < 8; i++) {
        int gr = rowBase + ty * 8 + i;
        if (gr < N) {
            *(float4*)&Cm[(size_t)gr * DIM + tx * 8]     =
                make_float4(acc[i][0], acc[i][1], acc[i][2], acc[i][3]);
            *(float4*)&Cm[(size_t)gr * DIM + tx * 8 + 4] =
                make_float4(acc[i][4], acc[i][5], acc[i][6], acc[i][7]);
        }
    }
}

// a_src[n,h] = dot(h[n,h,:], att_src[h,:]); same for a_dst
__global__ void attn_k(const float* __restrict__ hf, const float* __restrict__ atts,
                       const float* __restrict__ attd, float* __restrict__ asrc,
                       float* __restrict__ adst, int N) {
    int t = blockIdx.x * blockDim.x + threadIdx.x;
    if (t >= N * NH) return;
    int n = t >> 3, hd = t & 7;
    const float* hp = &hf[(size_t)n * DIM + hd * 16];
    const float* sp = &atts[hd * 16];
    const float* dp = &attd[hd * 16];
    float ss = 0.f, sd = 0.f;
#pragma unroll
    for (int q = 0; q < 16; q += 4) {
        float4 hv = *(const float4*)&hp[q];
        float4 sv = *(const float4*)&sp[q];
        float4 dv = *(const float4*)&dp[q];
        ss += hv.x * sv.x + hv.y * sv.y + hv.z * sv.z + hv.w * sv.w;
        sd += hv.x * dv.x + hv.y * dv.y + hv.z * dv.z + hv.w * dv.w;
    }
    asrc[t] = ss;
    adst[t] = sd;
}

// ---------------- CSR build ----------------
__global__ void init_cnt_k(int* __restrict__ cnt, int N) {
    int t = blockIdx.x * blockDim.x + threadIdx.x;
    if (t <= N) cnt[t] = (t < N) ? 1 : 0;   // 1 = self loop
}

__global__ void hist_k(const int* __restrict__ ei, int E, int* __restrict__ cnt) {
    int e = blockIdx.x * blockDim.x + threadIdx.x;
    if (e < E) atomicAdd(&cnt[ei[E + e]], 1);
}

// block sums: block b sums cnt[b*256 .. b*256+255]
__global__ void scan1_k(const int* __restrict__ cnt, int N, int* __restrict__ bsum) {
    __shared__ int sh[256];
    int t = threadIdx.x;
    int i = blockIdx.x * 256 + t;
    sh[t] = (i < N) ? cnt[i] : 0;
    __syncthreads();
    for (int off = 128; off > 0; off >>= 1) {
        if (t < off) sh[t] += sh[t + off];
        __syncthreads();
    }
    if (t == 0) bsum[blockIdx.x] = sh[0];
}

// exclusive scan of block sums (<=256 blocks)
__global__ void scan2_k(int* __restrict__ bsum, int nb) {
    __shared__ int sh[256];
    int t = threadIdx.x;
    int v = (t < nb) ? bsum[t] : 0;
    sh[t] = v;
    __syncthreads();
    for (int off = 1; off < 256; off <<= 1) {
        int x = (t >= off) ? sh[t - off] : 0;
        __syncthreads();
        sh[t] += x;
        __syncthreads();
    }
    if (t < nb) bsum[t] = sh[t] - v;   // exclusive
}

// local exclusive scan + block offset -> row_start; last element writes row[N]
__global__ void scan3_k(const int* __restrict__ cnt, int N,
                        const int* __restrict__ bsum, int* __restrict__ row) {
    __shared__ int sh[256];
    int t = threadIdx.x;
    int i = blockIdx.x * 256 + t;
    int v = (i < N) ? cnt[i] : 0;
    sh[t] = v;
    __syncthreads();
    for (int off = 1; off < 256; off <<= 1) {
        int x = (t >= off) ? sh[t - off] : 0;
        __syncthreads();
        sh[t] += x;
        __syncthreads();
    }
    int excl = sh[t] - v + bsum[blockIdx.x];
    if (i < N) row[i] = excl;
    if (i == N - 1) row[N] = excl + v;
}

// cursor init + place self loop at row start
__global__ void cursor_k(const int* __restrict__ row, int* __restrict__ cur,
                         int* __restrict__ csrc, int N) {
    int n = blockIdx.x * blockDim.x + threadIdx.x;
    if (n >= N) return;
    int r = row[n];
    csrc[r] = n;        // self loop first (deterministic position)
    cur[n] = r + 1;
}

__global__ void scatter_k(const int* __restrict__ ei, int E,
                          int* __restrict__ cur, int* __restrict__ csrc) {
    int e = blockIdx.x * blockDim.x + threadIdx.x;
    if (e >= E) return;
    int s = ei[e], d = ei[E + e];
    int pos = atomicAdd(&cur[d], 1);
    csrc[pos] = s;
}

// ---------------- fused per-node softmax + aggregation ----------------
// one warp per destination node; lane l owns output cols [4l, 4l+4), head l>>2
__global__ void gat_node_k(const int* __restrict__ csrc, const int* __restrict__ row,
                           const float* __restrict__ asrc, const float* __restrict__ adst,
                           const float* __restrict__ hf, const float* __restrict__ bias,
                           float* __restrict__ out, int N, int do_relu) {
    int warp = (blockIdx.x * blockDim.x + threadIdx.x) >> 5;
    int lane = threadIdx.x & 31;
    if (warp >= N) return;
    const int node = warp;
    const int beg = row[node], end = row[node + 1];

    float ad = (lane < NH) ? adst[node * NH + lane] : 0.f;

    // pass 1: per-head max over in-edges (lanes 0..7 active)
    float m = -__builtin_huge_valf();
    for (int e = beg; e < end; e++) {
        int s = csrc[e];                      // uniform (broadcast) load
        if (lane < NH) {
            float v = leaky(asrc[s * NH + lane] + ad);
            m = fmaxf(m, v);
        }
    }

    // pass 2: exp, denom, and register-resident aggregation
    const int hsel = lane >> 2;               // head of my 4 columns
    float den = 0.f;
    float a0 = 0.f, a1 = 0.f, a2 = 0.f, a3 = 0.f;
    for (int e = beg; e < end; e++) {
        int s = csrc[e];
        float v = 0.f;
        if (lane < NH)
            v = __expf(leaky(asrc[s * NH + lane] + ad) - m);
        den += v;
        float a = __shfl_sync(0xffffffffu, v, hsel);
        float4 hv = *(const float4*)&hf[(size_t)s * DIM + lane * 4];
        a0 += a * hv.x; a1 += a * hv.y; a2 += a * hv.z; a3 += a * hv.w;
    }
    float dd = __shfl_sync(0xffffffffu, den, hsel);
    float inv = 1.f / dd;
    float4 bv = *(const float4*)&bias[lane * 4];
    float4 o = make_float4(a0 * inv + bv.x, a1 * inv + bv.y,
                           a2 * inv + bv.z, a3 * inv + bv.w);
    if (do_relu) {
        o.x = fmaxf(o.x, 0.f); o.y = fmaxf(o.y, 0.f);
        o.z = fmaxf(o.z, 0.f); o.w = fmaxf(o.w, 0.f);
    }
    *(float4*)&out[(size_t)node * DIM + lane * 4] = o;
}

// ---------------- host ----------------
static void run_layer(const float* xin, int N,
                      const float* W, const float* as_, const float* ad_,
                      const float* bias, float* hbuf, float* asrc, float* adst,
                      const int* csrc, const int* row, float* outbuf, int do_relu) {
    gemm128<<<(N + 127) / 128, 256>>>(xin, W, hbuf, N);
    attn_k<<<(N * NH + 255) / 256, 256>>>(hbuf, as_, ad_, asrc, adst, N);
    gat_node_k<<<(N + 7) / 8, 256>>>(csrc, row, asrc, adst, hbuf, bias, outbuf, N, do_relu);
}

extern "C" void kernel_launch(void* const* d_in, const int* in_sizes, int n_in,
                              void* d_out, int out_size) {
    const float* x   = (const float*)d_in[0];
    const int*   ei  = (const int*)d_in[1];   // int32 (JAX x64 disabled)
    const float* W1  = (const float*)d_in[2];
    const float* as1 = (const float*)d_in[3];
    const float* ad1 = (const float*)d_in[4];
    const float* b1  = (const float*)d_in[5];
    const float* W2  = (const float*)d_in[6];
    const float* as2 = (const float*)d_in[7];
    const float* ad2 = (const float*)d_in[8];
    const float* b2  = (const float*)d_in[9];
    float* out = (float*)d_out;

    int N = in_sizes[0] / DIM;
    int E = in_sizes[1] / 2;

    float *hbuf, *x2, *asrc, *adst;
    int *cnt, *row, *cur, *bsum, *csrc;
    cudaGetSymbolAddress((void**)&hbuf, g_h);
    cudaGetSymbolAddress((void**)&x2,   g_x2);
    cudaGetSymbolAddress((void**)&asrc, g_asrc);
    cudaGetSymbolAddress((void**)&adst, g_adst);
    cudaGetSymbolAddress((void**)&cnt,  g_cnt);
    cudaGetSymbolAddress((void**)&row,  g_row);
    cudaGetSymbolAddress((void**)&cur,  g_cur);
    cudaGetSymbolAddress((void**)&bsum, g_bsum);
    cudaGetSymbolAddress((void**)&csrc, g_csrc);

    // ---- CSR build (dst-grouped), shared by both layers ----
    int nb = (N + 255) / 256;
    init_cnt_k<<<(N + 256) / 256, 256>>>(cnt, N);
    hist_k<<<(E + 255) / 256, 256>>>(ei, E, cnt);
    scan1_k<<<nb, 256>>>(cnt, N, bsum);
    scan2_k<<<1, 256>>>(bsum, nb);
    scan3_k<<<nb, 256>>>(cnt, N, bsum, row);
    cursor_k<<<(N + 255) / 256, 256>>>(row, cur, csrc, N);
    scatter_k<<<(E + 255) / 256, 256>>>(ei, E, cur, csrc);

    // ---- layer 1 (fused ReLU) -> x2 ----
    run_layer(x, N, W1, as1, ad1, b1, hbuf, asrc, adst, csrc, row, x2, 1);
    // ---- layer 2 -> d_out ----
    run_layer(x2, N, W2, as2, ad2, b2, hbuf, asrc, adst, csrc, row, out, 0);
}

// round 6
// speedup vs baseline: 3.0679x; 1.1577x over previous
#include <cuda_runtime.h>

#define DIM 128
#define NH  8
#define MAXN 50176
#define MAXT 1048576   // max edges incl. self loops

// ---------------- scratch (no allocations allowed) ----------------
__device__ float g_h[MAXN * DIM];
__device__ float g_x2[MAXN * DIM];
__device__ float g_asrc[MAXN * NH];
__device__ float g_adst[MAXN * NH];
__device__ int   g_cnt[MAXN + 1];
__device__ int   g_row[MAXN + 1];
__device__ int   g_cur[MAXN];
__device__ int   g_bsum[256];
__device__ int   g_csrc[MAXT];

__device__ __forceinline__ float leaky(float v) { return v > 0.f ? v : 0.2f * v; }

// ---- C[N,128] = A[N,128] * B[128,128], fused attention-coefficient epilogue ----
// a_src[n,h] = dot(Crow(n) head h, att_src[h,:]); same for a_dst.
__global__ void gemm128(const float* __restrict__ A, const float* __restrict__ B,
                        const float* __restrict__ atts, const float* __restrict__ attd,
                        float* __restrict__ Cm, float* __restrict__ asrc,
                        float* __restrict__ adst, int N) {
    __shared__ float As[8][128];
    __shared__ float Bs[8][128];
    const int tid = threadIdx.x;           // 256 threads
    const int tx = tid & 15;
    const int ty = tid >> 4;
    const int rowBase = blockIdx.x * 128;
    const int arow  = tid >> 1;
    const int akoff = (tid & 1) * 4;
    const int brow  = tid >> 5;
    const int bcol  = (tid & 31) * 4;

    float acc[8][8];
#pragma unroll
    for (int i = 0; i < 8; i++)
#pragma unroll
        for (int j = 0; j < 8; j++) acc[i][j] = 0.f;

    for (int k0 = 0; k0 < 128; k0 += 8) {
        float4 av = make_float4(0.f, 0.f, 0.f, 0.f);
        int gr = rowBase + arow;
        if (gr < N) av = *(const float4*)&A[(size_t)gr * DIM + k0 + akoff];
        As[akoff + 0][arow] = av.x;
        As[akoff + 1][arow] = av.y;
        As[akoff + 2][arow] = av.z;
        As[akoff + 3][arow] = av.w;
        *(float4*)&Bs[brow][bcol] = *(const float4*)&B[(size_t)(k0 + brow) * DIM + bcol];
        __syncthreads();
#pragma unroll
        for (int kr = 0; kr < 8; kr++) {
            float a[8], b[8];
#pragma unroll
            for (int i = 0; i < 8; i++) a[i] = As[kr][ty * 8 + i];
#pragma unroll
            for (int j = 0; j < 8; j++) b[j] = Bs[kr][tx * 8 + j];
#pragma unroll
            for (int i = 0; i < 8; i++)
#pragma unroll
                for (int j = 0; j < 8; j++) acc[i][j] += a[i] * b[j];
        }
        __syncthreads();
    }

    // store C
#pragma unroll
    for (int i = 0; i < 8; i++) {
        int gr = rowBase + ty * 8 + i;
        if (gr < N) {
            *(float4*)&Cm[(size_t)gr * DIM + tx * 8]     =
                make_float4(acc[i][0], acc[i][1], acc[i][2], acc[i][3]);
            *(float4*)&Cm[(size_t)gr * DIM + tx * 8 + 4] =
                make_float4(acc[i][4], acc[i][5], acc[i][6], acc[i][7]);
        }
    }

    // fused attention-coefficient epilogue.
    // This thread's 8 cols lie in head (tx>>1); col-within-head = (tx&1)*8 + j.
    const int head = tx >> 1;
    float sv[8], dv[8];
#pragma unroll
    for (int j = 0; j < 8; j++) {
        int off = (tx & 1) * 8 + j;
        sv[j] = atts[head * 16 + off];
        dv[j] = attd[head * 16 + off];
    }
#pragma unroll
    for (int i = 0; i < 8; i++) {
        float ss = 0.f, sd = 0.f;
#pragma unroll
        for (int j = 0; j < 8; j++) { ss += acc[i][j] * sv[j]; sd += acc[i][j] * dv[j]; }
        // pair (tx, tx^1) are adjacent lanes; reduce to full 16-wide head dot
        ss += __shfl_xor_sync(0xffffffffu, ss, 1);
        sd += __shfl_xor_sync(0xffffffffu, sd, 1);
        int gr = rowBase + ty * 8 + i;
        if ((tx & 1) == 0 && gr < N) {
            asrc[gr * NH + head] = ss;
            adst[gr * NH + head] = sd;
        }
    }
}

// ---------------- CSR build ----------------
__global__ void init_cnt_k(int* __restrict__ cnt, int N) {
    int t = blockIdx.x * blockDim.x + threadIdx.x;
    if (t <= N) cnt[t] = (t < N) ? 1 : 0;   // 1 = self loop
}

__global__ void hist_k(const int* __restrict__ ei, int E, int* __restrict__ cnt) {
    int e = blockIdx.x * blockDim.x + threadIdx.x;
    if (e < E) atomicAdd(&cnt[ei[E + e]], 1);
}

__global__ void scan1_k(const int* __restrict__ cnt, int N, int* __restrict__ bsum) {
    __shared__ int sh[256];
    int t = threadIdx.x;
    int i = blockIdx.x * 256 + t;
    sh[t] = (i < N) ? cnt[i] : 0;
    __syncthreads();
    for (int off = 128; off > 0; off >>= 1) {
        if (t < off) sh[t] += sh[t + off];
        __syncthreads();
    }
    if (t == 0) bsum[blockIdx.x] = sh[0];
}

__global__ void scan2_k(int* __restrict__ bsum, int nb) {
    __shared__ int sh[256];
    int t = threadIdx.x;
    int v = (t < nb) ? bsum[t] : 0;
    sh[t] = v;
    __syncthreads();
    for (int off = 1; off < 256; off <<= 1) {
        int x = (t >= off) ? sh[t - off] : 0;
        __syncthreads();
        sh[t] += x;
        __syncthreads();
    }
    if (t < nb) bsum[t] = sh[t] - v;   // exclusive
}

// local scan + block offset -> row offsets; also init cursors + self loops
__global__ void scan3_k(const int* __restrict__ cnt, int N,
                        const int* __restrict__ bsum, int* __restrict__ row,
                        int* __restrict__ cur, int* __restrict__ csrc) {
    __shared__ int sh[256];
    int t = threadIdx.x;
    int i = blockIdx.x * 256 + t;
    int v = (i < N) ? cnt[i] : 0;
    sh[t] = v;
    __syncthreads();
    for (int off = 1; off < 256; off <<= 1) {
        int x = (t >= off) ? sh[t - off] : 0;
        __syncthreads();
        sh[t] += x;
        __syncthreads();
    }
    int excl = sh[t] - v + bsum[blockIdx.x];
    if (i < N) {
        row[i] = excl;
        csrc[excl] = i;       // self loop first
        cur[i] = excl + 1;
    }
    if (i == N - 1) row[N] = excl + v;
}

__global__ void scatter_k(const int* __restrict__ ei, int E,
                          int* __restrict__ cur, int* __restrict__ csrc) {
    int e = blockIdx.x * blockDim.x + threadIdx.x;
    if (e >= E) return;
    int s = ei[e], d = ei[E + e];
    int pos = atomicAdd(&cur[d], 1);
    csrc[pos] = s;
}

// ---- fused per-node softmax + aggregation (single pass, no max subtraction) ----
// one warp per destination node; lane l owns output cols [4l, 4l+4), head l>>2
__global__ void gat_node_k(const int* __restrict__ csrc, const int* __restrict__ row,
                           const float* __restrict__ asrc, const float* __restrict__ adst,
                           const float* __restrict__ hf, const float* __restrict__ bias,
                           float* __restrict__ out, int N, int do_relu) {
    int warp = (blockIdx.x * blockDim.x + threadIdx.x) >> 5;
    int lane = threadIdx.x & 31;
    if (warp >= N) return;
    const int node = warp;
    const int beg = row[node], end = row[node + 1];

    const float ad = (lane < NH) ? adst[node * NH + lane] : 0.f;
    const int hsel = lane >> 2;

    float den = 0.f;
    float a0 = 0.f, a1 = 0.f, a2 = 0.f, a3 = 0.f;
    for (int e = beg; e < end; e++) {
        int s = csrc[e];                      // uniform broadcast load
        float v = 0.f;
        if (lane < NH)
            v = __expf(leaky(asrc[s * NH + lane] + ad));
        den += v;
        float a = __shfl_sync(0xffffffffu, v, hsel);
        float4 hv = *(const float4*)&hf[(size_t)s * DIM + lane * 4];
        a0 += a * hv.x; a1 += a * hv.y; a2 += a * hv.z; a3 += a * hv.w;
    }
    float dd = __shfl_sync(0xffffffffu, den, hsel);
    float inv = 1.f / dd;
    float4 bv = *(const float4*)&bias[lane * 4];
    float4 o = make_float4(a0 * inv + bv.x, a1 * inv + bv.y,
                           a2 * inv + bv.z, a3 * inv + bv.w);
    if (do_relu) {
        o.x = fmaxf(o.x, 0.f); o.y = fmaxf(o.y, 0.f);
        o.z = fmaxf(o.z, 0.f); o.w = fmaxf(o.w, 0.f);
    }
    *(float4*)&out[(size_t)node * DIM + lane * 4] = o;
}

// ---------------- host ----------------
static void run_layer(const float* xin, int N,
                      const float* W, const float* as_, const float* ad_,
                      const float* bias, float* hbuf, float* asrc, float* adst,
                      const int* csrc, const int* row, float* outbuf, int do_relu) {
    gemm128<<<(N + 127) / 128, 256>>>(xin, W, as_, ad_, hbuf, asrc, adst, N);
    gat_node_k<<<(N + 7) / 8, 256>>>(csrc, row, asrc, adst, hbuf, bias, outbuf, N, do_relu);
}

extern "C" void kernel_launch(void* const* d_in, const int* in_sizes, int n_in,
                              void* d_out, int out_size) {
    const float* x   = (const float*)d_in[0];
    const int*   ei  = (const int*)d_in[1];   // int32 (JAX x64 disabled)
    const float* W1  = (const float*)d_in[2];
    const float* as1 = (const float*)d_in[3];
    const float* ad1 = (const float*)d_in[4];
    const float* b1  = (const float*)d_in[5];
    const float* W2  = (const float*)d_in[6];
    const float* as2 = (const float*)d_in[7];
    const float* ad2 = (const float*)d_in[8];
    const float* b2  = (const float*)d_in[9];
    float* out = (float*)d_out;

    int N = in_sizes[0] / DIM;
    int E = in_sizes[1] / 2;

    float *hbuf, *x2, *asrc, *adst;
    int *cnt, *row, *cur, *bsum, *csrc;
    cudaGetSymbolAddress((void**)&hbuf, g_h);
    cudaGetSymbolAddress((void**)&x2,   g_x2);
    cudaGetSymbolAddress((void**)&asrc, g_asrc);
    cudaGetSymbolAddress((void**)&adst, g_adst);
    cudaGetSymbolAddress((void**)&cnt,  g_cnt);
    cudaGetSymbolAddress((void**)&row,  g_row);
    cudaGetSymbolAddress((void**)&cur,  g_cur);
    cudaGetSymbolAddress((void**)&bsum, g_bsum);
    cudaGetSymbolAddress((void**)&csrc, g_csrc);

    // ---- CSR build (dst-grouped), shared by both layers ----
    int nb = (N + 255) / 256;
    init_cnt_k<<<(N + 256) / 256, 256>>>(cnt, N);
    hist_k<<<(E + 255) / 256, 256>>>(ei, E, cnt);
    scan1_k<<<nb, 256>>>(cnt, N, bsum);
    scan2_k<<<1, 256>>>(bsum, nb);
    scan3_k<<<nb, 256>>>(cnt, N, bsum, row, cur, csrc);
    scatter_k<<<(E + 255) / 256, 256>>>(ei, E, cur, csrc);

    // ---- layer 1 (fused ReLU) -> x2 ----
    run_layer(x, N, W1, as1, ad1, b1, hbuf, asrc, adst, csrc, row, x2, 1);
    // ---- layer 2 -> d_out ----
    run_layer(x2, N, W2, as2, ad2, b2, hbuf, asrc, adst, csrc, row, out, 0);
}

// round 7
// speedup vs baseline: 3.6116x; 1.1772x over previous
#include <cuda_runtime.h>

#define DIM 128
#define NH  8
#define MAXN 50176
#define MAXT 1048576   // max edges incl. self loops

typedef unsigned long long u64;

// ---------------- scratch (no allocations allowed) ----------------
__device__ float g_h[MAXN * DIM];
__device__ float g_x2[MAXN * DIM];
__device__ float g_asrc[MAXN * NH];
__device__ float g_adst[MAXN * NH];
__device__ int   g_cnt[MAXN + 1];
__device__ int   g_row[MAXN + 1];
__device__ int   g_cur[MAXN];
__device__ int   g_bsum[256];
__device__ int   g_csrc[MAXT];

__device__ __forceinline__ float leaky(float v) { return v > 0.f ? v : 0.2f * v; }

// packed fp32x2 helpers (sm_100+; ptxas never auto-fuses these)
__device__ __forceinline__ u64 splat2(float x) {
    u64 r; asm("mov.b64 %0, {%1, %1};" : "=l"(r) : "f"(x)); return r;
}
__device__ __forceinline__ u64 ffma2(u64 a, u64 b, u64 c) {
    u64 d; asm("fma.rn.f32x2 %0, %1, %2, %3;" : "=l"(d) : "l"(a), "l"(b), "l"(c)); return d;
}
__device__ __forceinline__ float2 unpack2(u64 v) {
    float2 f; asm("mov.b64 {%0, %1}, %2;" : "=f"(f.x), "=f"(f.y) : "l"(v)); return f;
}

// ---- C[N,128] = A[N,128] * B[128,128], FFMA2 inner loop, fused attn epilogue ----
__global__ void gemm128(const float* __restrict__ A, const float* __restrict__ B,
                        const float* __restrict__ atts, const float* __restrict__ attd,
                        float* __restrict__ Cm, float* __restrict__ asrc,
                        float* __restrict__ adst, int N) {
    __shared__ float As[8][128];
    __shared__ float Bs[8][128];
    const int tid = threadIdx.x;           // 256 threads
    const int tx = tid & 15;
    const int ty = tid >> 4;
    const int rowBase = blockIdx.x * 128;
    const int arow  = tid >> 1;
    const int akoff = (tid & 1) * 4;
    const int brow  = tid >> 5;
    const int bcol  = (tid & 31) * 4;

    u64 acc2[8][4];
#pragma unroll
    for (int i = 0; i < 8; i++)
#pragma unroll
        for (int j = 0; j < 4; j++) acc2[i][j] = 0ull;

    for (int k0 = 0; k0 < 128; k0 += 8) {
        float4 av = make_float4(0.f, 0.f, 0.f, 0.f);
        int gr = rowBase + arow;
        if (gr < N) av = *(const float4*)&A[(size_t)gr * DIM + k0 + akoff];
        As[akoff + 0][arow] = av.x;
        As[akoff + 1][arow] = av.y;
        As[akoff + 2][arow] = av.z;
        As[akoff + 3][arow] = av.w;
        *(float4*)&Bs[brow][bcol] = *(const float4*)&B[(size_t)(k0 + brow) * DIM + bcol];
        __syncthreads();
#pragma unroll
        for (int kr = 0; kr < 8; kr++) {
            float4 a0 = *(const float4*)&As[kr][ty * 8];
            float4 a1 = *(const float4*)&As[kr][ty * 8 + 4];
            float a[8] = { a0.x, a0.y, a0.z, a0.w, a1.x, a1.y, a1.z, a1.w };
            ulonglong2 bq0 = *(const ulonglong2*)&Bs[kr][tx * 8];
            ulonglong2 bq1 = *(const ulonglong2*)&Bs[kr][tx * 8 + 4];
            u64 bp[4] = { bq0.x, bq0.y, bq1.x, bq1.y };
#pragma unroll
            for (int i = 0; i < 8; i++) {
                u64 as2 = splat2(a[i]);
#pragma unroll
                for (int jp = 0; jp < 4; jp++)
                    acc2[i][jp] = ffma2(as2, bp[jp], acc2[i][jp]);
            }
        }
        __syncthreads();
    }

    // unpack, store C, fused attention epilogue
    const int head = tx >> 1;
    float sv[8], dv[8];
#pragma unroll
    for (int j = 0; j < 8; j++) {
        int off = (tx & 1) * 8 + j;
        sv[j] = atts[head * 16 + off];
        dv[j] = attd[head * 16 + off];
    }
#pragma unroll
    for (int i = 0; i < 8; i++) {
        float2 c0 = unpack2(acc2[i][0]);
        float2 c1 = unpack2(acc2[i][1]);
        float2 c2 = unpack2(acc2[i][2]);
        float2 c3 = unpack2(acc2[i][3]);
        float c[8] = { c0.x, c0.y, c1.x, c1.y, c2.x, c2.y, c3.x, c3.y };
        int gr = rowBase + ty * 8 + i;
        if (gr < N) {
            *(float4*)&Cm[(size_t)gr * DIM + tx * 8]     = make_float4(c[0], c[1], c[2], c[3]);
            *(float4*)&Cm[(size_t)gr * DIM + tx * 8 + 4] = make_float4(c[4], c[5], c[6], c[7]);
        }
        float ss = 0.f, sd = 0.f;
#pragma unroll
        for (int j = 0; j < 8; j++) { ss += c[j] * sv[j]; sd += c[j] * dv[j]; }
        ss += __shfl_xor_sync(0xffffffffu, ss, 1);
        sd += __shfl_xor_sync(0xffffffffu, sd, 1);
        if ((tx & 1) == 0 && gr < N) {
            asrc[gr * NH + head] = ss;
            adst[gr * NH + head] = sd;
        }
    }
}

// ---------------- CSR build ----------------
__global__ void init_cnt_k(int* __restrict__ cnt, int N) {
    int t = blockIdx.x * blockDim.x + threadIdx.x;
    if (t <= N) cnt[t] = (t < N) ? 1 : 0;   // 1 = self loop
}

__global__ void hist_k(const int* __restrict__ ei, int E, int* __restrict__ cnt) {
    int e = blockIdx.x * blockDim.x + threadIdx.x;
    if (e < E) atomicAdd(&cnt[ei[E + e]], 1);
}

__global__ void scan1_k(const int* __restrict__ cnt, int N, int* __restrict__ bsum) {
    __shared__ int sh[256];
    int t = threadIdx.x;
    int i = blockIdx.x * 256 + t;
    sh[t] = (i < N) ? cnt[i] : 0;
    __syncthreads();
    for (int off = 128; off > 0; off >>= 1) {
        if (t < off) sh[t] += sh[t + off];
        __syncthreads();
    }
    if (t == 0) bsum[blockIdx.x] = sh[0];
}

__global__ void scan2_k(int* __restrict__ bsum, int nb) {
    __shared__ int sh[256];
    int t = threadIdx.x;
    int v = (t < nb) ? bsum[t] : 0;
    sh[t] = v;
    __syncthreads();
    for (int off = 1; off < 256; off <<= 1) {
        int x = (t >= off) ? sh[t - off] : 0;
        __syncthreads();
        sh[t] += x;
        __syncthreads();
    }
    if (t < nb) bsum[t] = sh[t] - v;   // exclusive
}

__global__ void scan3_k(const int* __restrict__ cnt, int N,
                        const int* __restrict__ bsum, int* __restrict__ row,
                        int* __restrict__ cur, int* __restrict__ csrc) {
    __shared__ int sh[256];
    int t = threadIdx.x;
    int i = blockIdx.x * 256 + t;
    int v = (i < N) ? cnt[i] : 0;
    sh[t] = v;
    __syncthreads();
    for (int off = 1; off < 256; off <<= 1) {
        int x = (t >= off) ? sh[t - off] : 0;
        __syncthreads();
        sh[t] += x;
        __syncthreads();
    }
    int excl = sh[t] - v + bsum[blockIdx.x];
    if (i < N) {
        row[i] = excl;
        csrc[excl] = i;       // self loop first
        cur[i] = excl + 1;
    }
    if (i == N - 1) row[N] = excl + v;
}

__global__ void scatter_k(const int* __restrict__ ei, int E,
                          int* __restrict__ cur, int* __restrict__ csrc) {
    int e = blockIdx.x * blockDim.x + threadIdx.x;
    if (e >= E) return;
    int s = ei[e], d = ei[E + e];
    int pos = atomicAdd(&cur[d], 1);
    csrc[pos] = s;
}

// ---- fused per-node softmax + aggregation (single pass, 2x unrolled) ----
// one warp per destination node; lane l owns output cols [4l, 4l+4), head l>>2
__global__ void gat_node_k(const int* __restrict__ csrc, const int* __restrict__ row,
                           const float* __restrict__ asrc, const float* __restrict__ adst,
                           const float* __restrict__ hf, const float* __restrict__ bias,
                           float* __restrict__ out, int N, int do_relu) {
    int warp = (blockIdx.x * blockDim.x + threadIdx.x) >> 5;
    int lane = threadIdx.x & 31;
    if (warp >= N) return;
    const int node = warp;
    const int beg = row[node], end = row[node + 1];

    const float ad = (lane < NH) ? adst[node * NH + lane] : 0.f;
    const int hsel = lane >> 2;

    float den = 0.f;
    float a0 = 0.f, a1 = 0.f, a2 = 0.f, a3 = 0.f;
    int e = beg;
    for (; e + 1 < end; e += 2) {
        int s0 = csrc[e], s1 = csrc[e + 1];
        float v0 = 0.f, v1 = 0.f;
        if (lane < NH) {
            v0 = __expf(leaky(asrc[s0 * NH + lane] + ad));
            v1 = __expf(leaky(asrc[s1 * NH + lane] + ad));
        }
        den += v0 + v1;
        float w0 = __shfl_sync(0xffffffffu, v0, hsel);
        float w1 = __shfl_sync(0xffffffffu, v1, hsel);
        float4 h0 = *(const float4*)&hf[(size_t)s0 * DIM + lane * 4];
        float4 h1 = *(const float4*)&hf[(size_t)s1 * DIM + lane * 4];
        a0 += w0 * h0.x + w1 * h1.x;
        a1 += w0 * h0.y + w1 * h1.y;
        a2 += w0 * h0.z + w1 * h1.z;
        a3 += w0 * h0.w + w1 * h1.w;
    }
    if (e < end) {
        int s = csrc[e];
        float v = 0.f;
        if (lane < NH) v = __expf(leaky(asrc[s * NH + lane] + ad));
        den += v;
        float w = __shfl_sync(0xffffffffu, v, hsel);
        float4 hv = *(const float4*)&hf[(size_t)s * DIM + lane * 4];
        a0 += w * hv.x; a1 += w * hv.y; a2 += w * hv.z; a3 += w * hv.w;
    }
    float dd = __shfl_sync(0xffffffffu, den, hsel);
    float inv = 1.f / dd;
    float4 bv = *(const float4*)&bias[lane * 4];
    float4 o = make_float4(a0 * inv + bv.x, a1 * inv + bv.y,
                           a2 * inv + bv.z, a3 * inv + bv.w);
    if (do_relu) {
        o.x = fmaxf(o.x, 0.f); o.y = fmaxf(o.y, 0.f);
        o.z = fmaxf(o.z, 0.f); o.w = fmaxf(o.w, 0.f);
    }
    *(float4*)&out[(size_t)node * DIM + lane * 4] = o;
}

// ---------------- host ----------------
static void run_layer(const float* xin, int N,
                      const float* W, const float* as_, const float* ad_,
                      const float* bias, float* hbuf, float* asrc, float* adst,
                      const int* csrc, const int* row, float* outbuf, int do_relu) {
    gemm128<<<(N + 127) / 128, 256>>>(xin, W, as_, ad_, hbuf, asrc, adst, N);
    gat_node_k<<<(N + 7) / 8, 256>>>(csrc, row, asrc, adst, hbuf, bias, outbuf, N, do_relu);
}

extern "C" void kernel_launch(void* const* d_in, const int* in_sizes, int n_in,
                              void* d_out, int out_size) {
    const float* x   = (const float*)d_in[0];
    const int*   ei  = (const int*)d_in[1];   // int32 (JAX x64 disabled)
    const float* W1  = (const float*)d_in[2];
    const float* as1 = (const float*)d_in[3];
    const float* ad1 = (const float*)d_in[4];
    const float* b1  = (const float*)d_in[5];
    const float* W2  = (const float*)d_in[6];
    const float* as2 = (const float*)d_in[7];
    const float* ad2 = (const float*)d_in[8];
    const float* b2  = (const float*)d_in[9];
    float* out = (float*)d_out;

    int N = in_sizes[0] / DIM;
    int E = in_sizes[1] / 2;

    float *hbuf, *x2, *asrc, *adst;
    int *cnt, *row, *cur, *bsum, *csrc;
    cudaGetSymbolAddress((void**)&hbuf, g_h);
    cudaGetSymbolAddress((void**)&x2,   g_x2);
    cudaGetSymbolAddress((void**)&asrc, g_asrc);
    cudaGetSymbolAddress((void**)&adst, g_adst);
    cudaGetSymbolAddress((void**)&cnt,  g_cnt);
    cudaGetSymbolAddress((void**)&row,  g_row);
    cudaGetSymbolAddress((void**)&cur,  g_cur);
    cudaGetSymbolAddress((void**)&bsum, g_bsum);
    cudaGetSymbolAddress((void**)&csrc, g_csrc);

    // ---- CSR build (dst-grouped), shared by both layers ----
    int nb = (N + 255) / 256;
    init_cnt_k<<<(N + 256) / 256, 256>>>(cnt, N);
    hist_k<<<(E + 255) / 256, 256>>>(ei, E, cnt);
    scan1_k<<<nb, 256>>>(cnt, N, bsum);
    scan2_k<<<1, 256>>>(bsum, nb);
    scan3_k<<<nb, 256>>>(cnt, N, bsum, row, cur, csrc);
    scatter_k<<<(E + 255) / 256, 256>>>(ei, E, cur, csrc);

    // ---- layer 1 (fused ReLU) -> x2 ----
    run_layer(x, N, W1, as1, ad1, b1, hbuf, asrc, adst, csrc, row, x2, 1);
    // ---- layer 2 -> d_out ----
    run_layer(x2, N, W2, as2, ad2, b2, hbuf, asrc, adst, csrc, row, out, 0);
}